// round 13
// baseline (speedup 1.0000x reference)
#include <cuda_runtime.h>
#include <cuda_fp16.h>
#include <math.h>
#include <stdint.h>

// Problem constants (fixed by the dataset)
#define NN   100000
#define EE   1600000
#define ETOT (EE + NN)          // edges + self loops
#define F1   128                // input features
#define F2   256                // HEADS*HID
#define NEG_SLOPE 0.2f

#define SCAN_BLK 1024
#define NBLKS ((NN + SCAN_BLK - 1) / SCAN_BLK)   // 98

// ---------------- scratch (device globals; no allocations allowed) ----------
__device__ __half g_h1h[(size_t)NN * F2]; // layer1 linear output, fp16 [N,256]
__device__ float g_as1[NN * 4];
__device__ float g_ad1[NN * 4];
__device__ float4 g_pk[NN];               // {as2, h3.x, h3.y, ad2} per node
__device__ int   g_cnt[NN];
__device__ int   g_rowptr[NN + 1];
__device__ int   g_cursor[NN];
__device__ int   g_bsum[NBLKS];
__device__ int   g_boff[NBLKS];
__device__ int   g_csr[ETOT];             // src node per incoming edge, grouped by dst

__device__ __forceinline__ float lrelu(float x) { return x > 0.f ? x : NEG_SLOPE * x; }
__device__ __forceinline__ float elu1(float x)  { return x > 0.f ? x : expm1f(x); }

// ---------------- CSR construction ------------------------------------------
__global__ void k_degree(const int* __restrict__ ei) {
    int i = blockIdx.x * blockDim.x + threadIdx.x;
    if (i < EE) atomicAdd(&g_cnt[ei[EE + i]], 1);
}

// ---- two-level parallel exclusive scan over (g_cnt + 1 self loop) ----------
__global__ __launch_bounds__(SCAN_BLK) void k_blocksum() {
    __shared__ int ws[32];
    int i = blockIdx.x * SCAN_BLK + threadIdx.x;
    int v = (i < NN) ? (g_cnt[i] + 1) : 0;
    int s = v;
    #pragma unroll
    for (int o = 16; o; o >>= 1) s += __shfl_xor_sync(0xffffffffu, s, o);
    if ((threadIdx.x & 31) == 0) ws[threadIdx.x >> 5] = s;
    __syncthreads();
    if (threadIdx.x < 32) {
        int t = ws[threadIdx.x];
        #pragma unroll
        for (int o = 16; o; o >>= 1) t += __shfl_xor_sync(0xffffffffu, t, o);
        if (threadIdx.x == 0) g_bsum[blockIdx.x] = t;
    }
}

__global__ void k_scanbsum() {
    __shared__ int sh[NBLKS];
    int t = threadIdx.x;
    if (t < NBLKS) sh[t] = g_bsum[t];
    __syncthreads();
    if (t == 0) {
        int run = 0;
        #pragma unroll 4
        for (int i = 0; i < NBLKS; i++) { int c = sh[i]; sh[i] = run; run += c; }
        g_rowptr[NN] = run;
    }
    __syncthreads();
    if (t < NBLKS) g_boff[t] = sh[t];
}

// writes rowptr, seeds cursor past the self-loop slot, and stores the
// self loop itself (csr[rowptr[i]] = i) -- scatter then only handles real edges
__global__ __launch_bounds__(SCAN_BLK) void k_writeptr() {
    __shared__ int ws[32];
    const int lane = threadIdx.x & 31;
    const int w    = threadIdx.x >> 5;
    int i = blockIdx.x * SCAN_BLK + threadIdx.x;
    int v = (i < NN) ? (g_cnt[i] + 1) : 0;
    int x = v;
    #pragma unroll
    for (int o = 1; o < 32; o <<= 1) {
        int y = __shfl_up_sync(0xffffffffu, x, o);
        if (lane >= o) x += y;
    }
    if (lane == 31) ws[w] = x;
    __syncthreads();
    if (threadIdx.x < 32) {
        int y = ws[threadIdx.x];
        #pragma unroll
        for (int o = 1; o < 32; o <<= 1) {
            int z = __shfl_up_sync(0xffffffffu, y, o);
            if (lane >= o) y += z;
        }
        ws[threadIdx.x] = y;
    }
    __syncthreads();
    int excl = x - v + ((w > 0) ? ws[w - 1] : 0) + g_boff[blockIdx.x];
    if (i < NN) {
        g_rowptr[i] = excl;
        g_csr[excl] = i;          // self loop in slot 0
        g_cursor[i] = excl + 1;
    }
}

__global__ void k_scatter(const int* __restrict__ ei) {
    int i = blockIdx.x * blockDim.x + threadIdx.x;
    if (i < EE) {
        int s = ei[i];
        int d = ei[EE + i];
        int p = atomicAdd(&g_cursor[d], 1);
        g_csr[p] = s;
    }
}

// ---------------- GEMM1 (single-pass tf32) + fused alpha epilogue -----------
// Fragment-layout smem: MMA operands staged in per-thread order so the inner
// loop does 5x LDS.128 per warp-ks instead of 20x LDS.32.
#define GBM 128
#define GBN 64
#define GBK 32

__device__ __forceinline__ uint32_t f2tf32(float f) {
    uint32_t r;
    asm("cvt.rna.tf32.f32 %0, %1;" : "=r"(r) : "f"(f));
    return r;
}
__device__ __forceinline__ void mma_tf32(float* c, uint32_t a0, uint32_t a1,
                                         uint32_t a2, uint32_t a3,
                                         uint32_t b0, uint32_t b1) {
    asm volatile(
        "mma.sync.aligned.m16n8k8.row.col.f32.tf32.tf32.f32 "
        "{%0,%1,%2,%3}, {%4,%5,%6,%7}, {%8,%9}, {%0,%1,%2,%3};"
        : "+f"(c[0]), "+f"(c[1]), "+f"(c[2]), "+f"(c[3])
        : "r"(a0), "r"(a1), "r"(a2), "r"(a3), "r"(b0), "r"(b1));
}

__global__ __launch_bounds__(256) void k_gemm1_tc(const float* __restrict__ A,
                                                  const float* __restrict__ B,
                                                  const float* __restrict__ aS1,
                                                  const float* __restrict__ aD1) {
    // A fragments: [wm][ks][lane][slot(4)] float4 each -> 2*4*32*4 float4
    // slot is swizzled: physical = (mt + ((lane>>1)&3)) & 3
    __shared__ float SAf[2 * 4 * 32 * 4 * 4];
    // B fragments: [wn][ks][lane] float4 -> 4*4*32 float4
    __shared__ float SBf[4 * 4 * 32 * 4];
    __shared__ float sAS[GBM][5];
    __shared__ float sAD[GBM][5];
    const int tid  = threadIdx.x;
    const int wid  = tid >> 5;
    const int lane = tid & 31;
    const int grp  = lane >> 2;
    const int tig  = lane & 3;
    const int wm   = wid & 1;
    const int wn   = wid >> 1;
    const int m0   = blockIdx.x * GBM;
    const int head = blockIdx.y;          // GBN == 64 == one head
    const int n0   = head * GBN;
    const int lsw  = (lane >> 1) & 3;     // read-side swizzle component

    float acc[4][2][4];
    #pragma unroll
    for (int i = 0; i < 4; i++)
        #pragma unroll
        for (int j = 0; j < 2; j++)
            #pragma unroll
            for (int k = 0; k < 4; k++) acc[i][j][k] = 0.f;

    float4 pa[4], pb[2];
    auto loadA = [&](int k0, float4* r) {
        #pragma unroll
        for (int i = 0; i < 4; i++) {
            int f = tid + i * 256;
            int row = f >> 3, c4 = f & 7;
            int gr = m0 + row;
            r[i] = (gr < NN) ? *(const float4*)(A + (size_t)gr * F1 + k0 + 4 * c4)
                             : make_float4(0.f, 0.f, 0.f, 0.f);
        }
    };
    auto loadB = [&](int k0, float4* r) {
        #pragma unroll
        for (int i = 0; i < 2; i++) {
            int f = tid + i * 256;
            int row = f >> 4, c4 = f & 15;
            r[i] = *(const float4*)(B + (size_t)(k0 + row) * F2 + n0 + 4 * c4);
        }
    };

    loadA(0, pa);
    loadB(0, pb);

    for (int k0 = 0; k0 < F1; k0 += GBK) {
        // ---- stage A into fragment layout ----
        #pragma unroll
        for (int i = 0; i < 4; i++) {
            int f = tid + i * 256;
            int row = f >> 3, c4 = f & 7;
            int wmv = row >> 6, mt = (row >> 4) & 3, i8 = (row >> 3) & 1, gp = row & 7;
            int ks = c4 >> 1, kh = c4 & 1;
            int reg = kh * 2 + i8;
            const float* v = (const float*)&pa[i];
            #pragma unroll
            for (int j = 0; j < 4; j++) {
                int ln = gp * 4 + j;                       // tig = j
                int slot = (mt + ((ln >> 1) & 3)) & 3;     // swizzle
                SAf[((((wmv * 4 + ks) * 32 + ln) * 4 + slot) << 2) + reg] = v[j];
            }
        }
        // ---- stage B into fragment layout ----
        #pragma unroll
        for (int i = 0; i < 2; i++) {
            int f = tid + i * 256;
            int row = f >> 4, c4 = f & 15;
            int wnv = c4 >> 2;
            int colb = 4 * c4;
            int nt = (colb >> 3) & 1;
            int gp0 = colb & 7;
            int tg = row & 3, kh = (row >> 2) & 1, ks = row >> 3;
            int slot = nt * 2 + kh;
            const float* v = (const float*)&pb[i];
            #pragma unroll
            for (int j = 0; j < 4; j++) {
                int ln = (gp0 + j) * 4 + tg;
                SBf[(((wnv * 4 + ks) * 32 + ln) << 2) + slot] = v[j];
            }
        }
        __syncthreads();

        if (k0 + GBK < F1) {
            loadA(k0 + GBK, pa);
            loadB(k0 + GBK, pb);
        }

        #pragma unroll
        for (int ks = 0; ks < GBK / 8; ks++) {
            float4 bv = *(const float4*)(SBf + (((wn * 4 + ks) * 32 + lane) << 2));
            uint32_t b00 = f2tf32(bv.x), b01 = f2tf32(bv.y);
            uint32_t b10 = f2tf32(bv.z), b11 = f2tf32(bv.w);
            #pragma unroll
            for (int mt = 0; mt < 4; mt++) {
                int slot = (mt + lsw) & 3;
                float4 av = *(const float4*)(
                    SAf + ((((wm * 4 + ks) * 32 + lane) * 4 + slot) << 2));
                uint32_t a0 = f2tf32(av.x), a1 = f2tf32(av.y);
                uint32_t a2 = f2tf32(av.z), a3 = f2tf32(av.w);
                mma_tf32(acc[mt][0], a0, a1, a2, a3, b00, b01);
                mma_tf32(acc[mt][1], a0, a1, a2, a3, b10, b11);
            }
        }
        __syncthreads();
    }

    float asv[2][2], adv[2][2];
    #pragma unroll
    for (int nt = 0; nt < 2; nt++) {
        int c = head * 64 + wn * 16 + nt * 8 + 2 * tig;
        asv[nt][0] = aS1[c];     asv[nt][1] = aS1[c + 1];
        adv[nt][0] = aD1[c];     adv[nt][1] = aD1[c + 1];
    }

    #pragma unroll
    for (int mt = 0; mt < 4; mt++) {
        int r = m0 + wm * 64 + mt * 16 + grp;
        float sS0 = 0.f, sS8 = 0.f, sD0 = 0.f, sD8 = 0.f;
        #pragma unroll
        for (int nt = 0; nt < 2; nt++) {
            int c = n0 + wn * 16 + nt * 8 + 2 * tig;
            if (r < NN)
                *(__half2*)(g_h1h + (size_t)r * F2 + c) =
                    __floats2half2_rn(acc[mt][nt][0], acc[mt][nt][1]);
            if (r + 8 < NN)
                *(__half2*)(g_h1h + (size_t)(r + 8) * F2 + c) =
                    __floats2half2_rn(acc[mt][nt][2], acc[mt][nt][3]);
            sS0 += acc[mt][nt][0] * asv[nt][0] + acc[mt][nt][1] * asv[nt][1];
            sS8 += acc[mt][nt][2] * asv[nt][0] + acc[mt][nt][3] * asv[nt][1];
            sD0 += acc[mt][nt][0] * adv[nt][0] + acc[mt][nt][1] * adv[nt][1];
            sD8 += acc[mt][nt][2] * adv[nt][0] + acc[mt][nt][3] * adv[nt][1];
        }
        #pragma unroll
        for (int o = 1; o <= 2; o <<= 1) {
            sS0 += __shfl_xor_sync(0xffffffffu, sS0, o);
            sS8 += __shfl_xor_sync(0xffffffffu, sS8, o);
            sD0 += __shfl_xor_sync(0xffffffffu, sD0, o);
            sD8 += __shfl_xor_sync(0xffffffffu, sD8, o);
        }
        if (tig == 0) {
            int rl = wm * 64 + mt * 16 + grp;
            sAS[rl][wn] = sS0;  sAS[rl + 8][wn] = sS8;
            sAD[rl][wn] = sD0;  sAD[rl + 8][wn] = sD8;
        }
    }
    __syncthreads();
    if (tid < GBM) {
        int r = m0 + tid;
        if (r < NN) {
            float aS = sAS[tid][0] + sAS[tid][1] + sAS[tid][2] + sAS[tid][3];
            float aD = sAD[tid][0] + sAD[tid][1] + sAD[tid][2] + sAD[tid][3];
            g_as1[4 * r + head] = aS;
            g_ad1[4 * r + head] = aD;
        }
    }
}

// ---------------- layer-1 softmax+aggregate + layer-2 linear (warp per dst) -
__global__ __launch_bounds__(256) void k_agg1f(const float* __restrict__ b1,
                                               const float* __restrict__ W2,
                                               const float* __restrict__ aS2,
                                               const float* __restrict__ aD2) {
    int n = (blockIdx.x * blockDim.x + threadIdx.x) >> 5;
    int lane = threadIdx.x & 31;
    if (n >= NN) return;
    int beg = g_rowptr[n], end = g_rowptr[n + 1];
    const int head = lane >> 3;
    float ad_h = g_ad1[4 * n + head];
    const __half* h1base = g_h1h + 8 * lane;

    float acc[8] = {0, 0, 0, 0, 0, 0, 0, 0};
    float ssum = 0.f;

    int e = beg;
    for (; e + 8 <= end; e += 8) {
        int   si[8];
        float av[8];
        uint4 hv[8];
        #pragma unroll
        for (int k = 0; k < 8; k++) si[k] = g_csr[e + k];
        #pragma unroll
        for (int k = 0; k < 8; k++) av[k] = g_as1[4 * si[k] + head];
        #pragma unroll
        for (int k = 0; k < 8; k++) hv[k] = *(const uint4*)(h1base + (size_t)si[k] * F2);
        #pragma unroll
        for (int k = 0; k < 8; k++) {
            float w = __expf(lrelu(av[k] + ad_h));
            ssum += w;
            const __half2* hp = (const __half2*)&hv[k];
            #pragma unroll
            for (int j = 0; j < 4; j++) {
                float2 f = __half22float2(hp[j]);
                acc[2 * j]     += f.x * w;
                acc[2 * j + 1] += f.y * w;
            }
        }
    }
    for (; e < end; e++) {
        int s = g_csr[e];
        float w = __expf(lrelu(g_as1[4 * s + head] + ad_h));
        uint4 hvv = *(const uint4*)(h1base + (size_t)s * F2);
        const __half2* hp = (const __half2*)&hvv;
        ssum += w;
        #pragma unroll
        for (int j = 0; j < 4; j++) {
            float2 f = __half22float2(hp[j]);
            acc[2 * j]     += f.x * w;
            acc[2 * j + 1] += f.y * w;
        }
    }
    float r = 1.f / ssum;

    const int fb = 8 * lane;
    float4 bb0 = *(const float4*)(b1 + fb);
    float4 bb1 = *(const float4*)(b1 + fb + 4);
    float s0 = 0.f, s1 = 0.f;
    #pragma unroll
    for (int j = 0; j < 8; j++) {
        float bj = (j < 4) ? (&bb0.x)[j] : (&bb1.x)[j - 4];
        float h2 = elu1(acc[j] * r + bj);
        float2 w2 = *(const float2*)(W2 + 2 * (fb + j));
        s0 += h2 * w2.x;
        s1 += h2 * w2.y;
    }
    #pragma unroll
    for (int o = 16; o; o >>= 1) {
        s0 += __shfl_xor_sync(0xffffffffu, s0, o);
        s1 += __shfl_xor_sync(0xffffffffu, s1, o);
    }
    if (lane == 0) {
        float as2v = s0 * aS2[0] + s1 * aS2[1];
        float ad2v = s0 * aD2[0] + s1 * aD2[1];
        g_pk[n] = make_float4(as2v, s0, s1, ad2v);
    }
}

// ---------------- layer-2 fused softmax+aggregate (warp per dst, ONE pass) --
__global__ __launch_bounds__(256) void k_agg2f(float* __restrict__ out,
                                               const float* __restrict__ b2) {
    int n = (blockIdx.x * blockDim.x + threadIdx.x) >> 5;
    int lane = threadIdx.x & 31;
    if (n >= NN) return;
    int beg = g_rowptr[n], end = g_rowptr[n + 1];
    float adv = g_pk[n].w;

    float s = 0, p0 = 0, p1 = 0;
    for (int e = beg + lane; e < end; e += 32) {
        int sn = g_csr[e];
        float4 pk = g_pk[sn];
        float ex = __expf(lrelu(pk.x + adv));
        s += ex;
        p0 += ex * pk.y;
        p1 += ex * pk.z;
    }
    #pragma unroll
    for (int o = 16; o; o >>= 1) {
        s  += __shfl_xor_sync(0xffffffffu, s, o);
        p0 += __shfl_xor_sync(0xffffffffu, p0, o);
        p1 += __shfl_xor_sync(0xffffffffu, p1, o);
    }
    if (lane == 0) {
        float inv = 1.f / s;
        out[2 * n]     = p0 * inv + b2[0];
        out[2 * n + 1] = p1 * inv + b2[1];
    }
}

// ---------------- launch ----------------------------------------------------
extern "C" void kernel_launch(void* const* d_in, const int* in_sizes, int n_in,
                              void* d_out, int out_size) {
    const float* x   = (const float*)d_in[0];
    const int*   ei  = (const int*)  d_in[1];
    const float* W1  = (const float*)d_in[2];
    const float* aS1 = (const float*)d_in[3];
    const float* aD1 = (const float*)d_in[4];
    const float* b1  = (const float*)d_in[5];
    const float* W2  = (const float*)d_in[6];
    const float* aS2 = (const float*)d_in[7];
    const float* aD2 = (const float*)d_in[8];
    const float* b2  = (const float*)d_in[9];
    float* out = (float*)d_out;

    // Fork a side stream so GEMM1 (depends only on x, W1) overlaps the CSR
    // build inside the captured graph.
    cudaStream_t s2;
    cudaStreamCreateWithFlags(&s2, cudaStreamNonBlocking);
    cudaEvent_t evFork, evJoin;
    cudaEventCreateWithFlags(&evFork, cudaEventDisableTiming);
    cudaEventCreateWithFlags(&evJoin, cudaEventDisableTiming);

    cudaEventRecord(evFork, 0);
    cudaStreamWaitEvent(s2, evFork, 0);

    // branch A (s2): layer-1 GEMM + fused alphas
    k_gemm1_tc<<<dim3((NN + GBM - 1) / GBM, F2 / GBN), 256, 0, s2>>>(x, W1, aS1, aD1);
    cudaEventRecord(evJoin, s2);

    // branch B (default): CSR build
    void* cntPtr = nullptr;
    cudaGetSymbolAddress(&cntPtr, g_cnt);
    cudaMemsetAsync(cntPtr, 0, NN * sizeof(int), 0);
    k_degree<<<(EE + 255) / 256, 256>>>(ei);
    k_blocksum<<<NBLKS, SCAN_BLK>>>();
    k_scanbsum<<<1, 128>>>();
    k_writeptr<<<NBLKS, SCAN_BLK>>>();
    k_scatter<<<(EE + 255) / 256, 256>>>(ei);

    // join
    cudaStreamWaitEvent(0, evJoin, 0);

    // layer-1 aggregate fused with layer-2 linear
    int warpGrid = (NN * 32 + 255) / 256;
    k_agg1f<<<warpGrid, 256>>>(b1, W2, aS2, aD2);

    // layer-2 aggregate
    k_agg2f<<<warpGrid, 256>>>(out, b2);
}

// round 14
// speedup vs baseline: 1.1924x; 1.1924x over previous
#include <cuda_runtime.h>
#include <cuda_fp16.h>
#include <math.h>
#include <stdint.h>

// Problem constants (fixed by the dataset)
#define NN   100000
#define EE   1600000
#define ETOT (EE + NN)          // edges + self loops
#define F1   128                // input features
#define F2   256                // HEADS*HID
#define NEG_SLOPE 0.2f

#define SCAN_BLK 1024
#define NBLKS ((NN + SCAN_BLK - 1) / SCAN_BLK)   // 98

// ---------------- scratch (device globals; no allocations allowed) ----------
__device__ __half g_h1h[(size_t)NN * F2]; // layer1 linear output, fp16 [N,256]
__device__ float g_as1[NN * 4];
__device__ float g_ad1[NN * 4];
__device__ float4 g_pk[NN];               // {as2, h3.x, h3.y, ad2} per node
__device__ int   g_cnt[NN];
__device__ int   g_rowptr[NN + 1];
__device__ int   g_cursor[NN];
__device__ int   g_bsum[NBLKS];
__device__ int   g_boff[NBLKS];
__device__ int   g_csr[ETOT];             // src node per incoming edge, grouped by dst

__device__ __forceinline__ float lrelu(float x) { return x > 0.f ? x : NEG_SLOPE * x; }
__device__ __forceinline__ float elu1(float x)  { return x > 0.f ? x : expm1f(x); }

// ---------------- CSR construction ------------------------------------------
__global__ void k_degree(const int* __restrict__ ei) {
    int i = blockIdx.x * blockDim.x + threadIdx.x;
    if (i < EE) atomicAdd(&g_cnt[ei[EE + i]], 1);
}

// ---- two-level parallel exclusive scan over (g_cnt + 1 self loop) ----------
__global__ __launch_bounds__(SCAN_BLK) void k_blocksum() {
    __shared__ int ws[32];
    int i = blockIdx.x * SCAN_BLK + threadIdx.x;
    int v = (i < NN) ? (g_cnt[i] + 1) : 0;
    int s = v;
    #pragma unroll
    for (int o = 16; o; o >>= 1) s += __shfl_xor_sync(0xffffffffu, s, o);
    if ((threadIdx.x & 31) == 0) ws[threadIdx.x >> 5] = s;
    __syncthreads();
    if (threadIdx.x < 32) {
        int t = ws[threadIdx.x];
        #pragma unroll
        for (int o = 16; o; o >>= 1) t += __shfl_xor_sync(0xffffffffu, t, o);
        if (threadIdx.x == 0) g_bsum[blockIdx.x] = t;
    }
}

__global__ void k_scanbsum() {
    __shared__ int sh[NBLKS];
    int t = threadIdx.x;
    if (t < NBLKS) sh[t] = g_bsum[t];
    __syncthreads();
    if (t == 0) {
        int run = 0;
        #pragma unroll 4
        for (int i = 0; i < NBLKS; i++) { int c = sh[i]; sh[i] = run; run += c; }
        g_rowptr[NN] = run;
    }
    __syncthreads();
    if (t < NBLKS) g_boff[t] = sh[t];
}

// writes rowptr, seeds cursor past the self-loop slot, and stores the
// self loop itself (csr[rowptr[i]] = i) -- scatter then only handles real edges
__global__ __launch_bounds__(SCAN_BLK) void k_writeptr() {
    __shared__ int ws[32];
    const int lane = threadIdx.x & 31;
    const int w    = threadIdx.x >> 5;
    int i = blockIdx.x * SCAN_BLK + threadIdx.x;
    int v = (i < NN) ? (g_cnt[i] + 1) : 0;
    int x = v;
    #pragma unroll
    for (int o = 1; o < 32; o <<= 1) {
        int y = __shfl_up_sync(0xffffffffu, x, o);
        if (lane >= o) x += y;
    }
    if (lane == 31) ws[w] = x;
    __syncthreads();
    if (threadIdx.x < 32) {
        int y = ws[threadIdx.x];
        #pragma unroll
        for (int o = 1; o < 32; o <<= 1) {
            int z = __shfl_up_sync(0xffffffffu, y, o);
            if (lane >= o) y += z;
        }
        ws[threadIdx.x] = y;
    }
    __syncthreads();
    int excl = x - v + ((w > 0) ? ws[w - 1] : 0) + g_boff[blockIdx.x];
    if (i < NN) {
        g_rowptr[i] = excl;
        g_csr[excl] = i;          // self loop in slot 0
        g_cursor[i] = excl + 1;
    }
}

__global__ void k_scatter(const int* __restrict__ ei) {
    int i = blockIdx.x * blockDim.x + threadIdx.x;
    if (i < EE) {
        int s = ei[i];
        int d = ei[EE + i];
        int p = atomicAdd(&g_cursor[d], 1);
        g_csr[p] = s;
    }
}

// ---------------- GEMM1 (single-pass tf32) + fused alpha epilogue -----------
// (R12 version: padded-scalar smem staging, proven fastest)
#define GBM 128
#define GBN 64
#define GBK 32
#define ASTRIDE 36
#define BSTRIDE 72

__device__ __forceinline__ uint32_t f2tf32(float f) {
    uint32_t r;
    asm("cvt.rna.tf32.f32 %0, %1;" : "=r"(r) : "f"(f));
    return r;
}
__device__ __forceinline__ void mma_tf32(float* c, uint32_t a0, uint32_t a1,
                                         uint32_t a2, uint32_t a3,
                                         uint32_t b0, uint32_t b1) {
    asm volatile(
        "mma.sync.aligned.m16n8k8.row.col.f32.tf32.tf32.f32 "
        "{%0,%1,%2,%3}, {%4,%5,%6,%7}, {%8,%9}, {%0,%1,%2,%3};"
        : "+f"(c[0]), "+f"(c[1]), "+f"(c[2]), "+f"(c[3])
        : "r"(a0), "r"(a1), "r"(a2), "r"(a3), "r"(b0), "r"(b1));
}

__global__ __launch_bounds__(256) void k_gemm1_tc(const float* __restrict__ A,
                                                  const float* __restrict__ B,
                                                  const float* __restrict__ aS1,
                                                  const float* __restrict__ aD1) {
    __shared__ float As[GBM * ASTRIDE];
    __shared__ float Bs[GBK * BSTRIDE];
    __shared__ float sAS[GBM][5];
    __shared__ float sAD[GBM][5];
    const int tid  = threadIdx.x;
    const int wid  = tid >> 5;
    const int lane = tid & 31;
    const int grp  = lane >> 2;
    const int tig  = lane & 3;
    const int wm   = wid & 1;
    const int wn   = wid >> 1;
    const int m0   = blockIdx.x * GBM;
    const int head = blockIdx.y;          // GBN == 64 == one head
    const int n0   = head * GBN;

    float acc[4][2][4];
    #pragma unroll
    for (int i = 0; i < 4; i++)
        #pragma unroll
        for (int j = 0; j < 2; j++)
            #pragma unroll
            for (int k = 0; k < 4; k++) acc[i][j][k] = 0.f;

    float4 pa[4], pb[2];
    auto loadA = [&](int k0, float4* r) {
        #pragma unroll
        for (int i = 0; i < 4; i++) {
            int f = tid + i * 256;
            int row = f >> 3, c4 = f & 7;
            int gr = m0 + row;
            r[i] = (gr < NN) ? *(const float4*)(A + (size_t)gr * F1 + k0 + 4 * c4)
                             : make_float4(0.f, 0.f, 0.f, 0.f);
        }
    };
    auto loadB = [&](int k0, float4* r) {
        #pragma unroll
        for (int i = 0; i < 2; i++) {
            int f = tid + i * 256;
            int row = f >> 4, c4 = f & 15;
            r[i] = *(const float4*)(B + (size_t)(k0 + row) * F2 + n0 + 4 * c4);
        }
    };

    loadA(0, pa);
    loadB(0, pb);

    for (int k0 = 0; k0 < F1; k0 += GBK) {
        #pragma unroll
        for (int i = 0; i < 4; i++) {
            int f = tid + i * 256;
            int row = f >> 3, c4 = f & 7;
            *(float4*)(As + row * ASTRIDE + 4 * c4) = pa[i];
        }
        #pragma unroll
        for (int i = 0; i < 2; i++) {
            int f = tid + i * 256;
            int row = f >> 4, c4 = f & 15;
            *(float4*)(Bs + row * BSTRIDE + 4 * c4) = pb[i];
        }
        __syncthreads();

        if (k0 + GBK < F1) {
            loadA(k0 + GBK, pa);
            loadB(k0 + GBK, pb);
        }

        #pragma unroll
        for (int ks = 0; ks < GBK / 8; ks++) {
            const int kb = ks * 8;
            uint32_t am[4][4];
            #pragma unroll
            for (int mt = 0; mt < 4; mt++) {
                int r = wm * 64 + mt * 16 + grp;
                am[mt][0] = f2tf32(As[r * ASTRIDE + kb + tig]);
                am[mt][1] = f2tf32(As[(r + 8) * ASTRIDE + kb + tig]);
                am[mt][2] = f2tf32(As[r * ASTRIDE + kb + tig + 4]);
                am[mt][3] = f2tf32(As[(r + 8) * ASTRIDE + kb + tig + 4]);
            }
            uint32_t bm[2][2];
            #pragma unroll
            for (int nt = 0; nt < 2; nt++) {
                int c = wn * 16 + nt * 8 + grp;
                bm[nt][0] = f2tf32(Bs[(kb + tig) * BSTRIDE + c]);
                bm[nt][1] = f2tf32(Bs[(kb + tig + 4) * BSTRIDE + c]);
            }
            #pragma unroll
            for (int mt = 0; mt < 4; mt++)
                #pragma unroll
                for (int nt = 0; nt < 2; nt++)
                    mma_tf32(acc[mt][nt], am[mt][0], am[mt][1], am[mt][2], am[mt][3],
                             bm[nt][0], bm[nt][1]);
        }
        __syncthreads();
    }

    float asv[2][2], adv[2][2];
    #pragma unroll
    for (int nt = 0; nt < 2; nt++) {
        int c = head * 64 + wn * 16 + nt * 8 + 2 * tig;
        asv[nt][0] = aS1[c];     asv[nt][1] = aS1[c + 1];
        adv[nt][0] = aD1[c];     adv[nt][1] = aD1[c + 1];
    }

    #pragma unroll
    for (int mt = 0; mt < 4; mt++) {
        int r = m0 + wm * 64 + mt * 16 + grp;
        float sS0 = 0.f, sS8 = 0.f, sD0 = 0.f, sD8 = 0.f;
        #pragma unroll
        for (int nt = 0; nt < 2; nt++) {
            int c = n0 + wn * 16 + nt * 8 + 2 * tig;
            if (r < NN)
                *(__half2*)(g_h1h + (size_t)r * F2 + c) =
                    __floats2half2_rn(acc[mt][nt][0], acc[mt][nt][1]);
            if (r + 8 < NN)
                *(__half2*)(g_h1h + (size_t)(r + 8) * F2 + c) =
                    __floats2half2_rn(acc[mt][nt][2], acc[mt][nt][3]);
            sS0 += acc[mt][nt][0] * asv[nt][0] + acc[mt][nt][1] * asv[nt][1];
            sS8 += acc[mt][nt][2] * asv[nt][0] + acc[mt][nt][3] * asv[nt][1];
            sD0 += acc[mt][nt][0] * adv[nt][0] + acc[mt][nt][1] * adv[nt][1];
            sD8 += acc[mt][nt][2] * adv[nt][0] + acc[mt][nt][3] * adv[nt][1];
        }
        #pragma unroll
        for (int o = 1; o <= 2; o <<= 1) {
            sS0 += __shfl_xor_sync(0xffffffffu, sS0, o);
            sS8 += __shfl_xor_sync(0xffffffffu, sS8, o);
            sD0 += __shfl_xor_sync(0xffffffffu, sD0, o);
            sD8 += __shfl_xor_sync(0xffffffffu, sD8, o);
        }
        if (tig == 0) {
            int rl = wm * 64 + mt * 16 + grp;
            sAS[rl][wn] = sS0;  sAS[rl + 8][wn] = sS8;
            sAD[rl][wn] = sD0;  sAD[rl + 8][wn] = sD8;
        }
    }
    __syncthreads();
    if (tid < GBM) {
        int r = m0 + tid;
        if (r < NN) {
            float aS = sAS[tid][0] + sAS[tid][1] + sAS[tid][2] + sAS[tid][3];
            float aD = sAD[tid][0] + sAD[tid][1] + sAD[tid][2] + sAD[tid][3];
            g_as1[4 * r + head] = aS;
            g_ad1[4 * r + head] = aD;
        }
    }
}

// ---------------- layer-1 softmax+aggregate + layer-2 linear (warp per dst) -
__global__ __launch_bounds__(256) void k_agg1f(const float* __restrict__ b1,
                                               const float* __restrict__ W2,
                                               const float* __restrict__ aS2,
                                               const float* __restrict__ aD2) {
    int n = (blockIdx.x * blockDim.x + threadIdx.x) >> 5;
    int lane = threadIdx.x & 31;
    if (n >= NN) return;
    int beg = g_rowptr[n], end = g_rowptr[n + 1];
    const int head = lane >> 3;
    float ad_h = g_ad1[4 * n + head];
    const __half* h1base = g_h1h + 8 * lane;

    float acc[8] = {0, 0, 0, 0, 0, 0, 0, 0};
    float ssum = 0.f;

    int e = beg;
    for (; e + 8 <= end; e += 8) {
        int   si[8];
        float av[8];
        uint4 hv[8];
        #pragma unroll
        for (int k = 0; k < 8; k++) si[k] = g_csr[e + k];
        #pragma unroll
        for (int k = 0; k < 8; k++) av[k] = g_as1[4 * si[k] + head];
        #pragma unroll
        for (int k = 0; k < 8; k++) hv[k] = *(const uint4*)(h1base + (size_t)si[k] * F2);
        #pragma unroll
        for (int k = 0; k < 8; k++) {
            float w = __expf(lrelu(av[k] + ad_h));
            ssum += w;
            const __half2* hp = (const __half2*)&hv[k];
            #pragma unroll
            for (int j = 0; j < 4; j++) {
                float2 f = __half22float2(hp[j]);
                acc[2 * j]     += f.x * w;
                acc[2 * j + 1] += f.y * w;
            }
        }
    }
    for (; e < end; e++) {
        int s = g_csr[e];
        float w = __expf(lrelu(g_as1[4 * s + head] + ad_h));
        uint4 hvv = *(const uint4*)(h1base + (size_t)s * F2);
        const __half2* hp = (const __half2*)&hvv;
        ssum += w;
        #pragma unroll
        for (int j = 0; j < 4; j++) {
            float2 f = __half22float2(hp[j]);
            acc[2 * j]     += f.x * w;
            acc[2 * j + 1] += f.y * w;
        }
    }
    float r = 1.f / ssum;

    const int fb = 8 * lane;
    float4 bb0 = *(const float4*)(b1 + fb);
    float4 bb1 = *(const float4*)(b1 + fb + 4);
    float s0 = 0.f, s1 = 0.f;
    #pragma unroll
    for (int j = 0; j < 8; j++) {
        float bj = (j < 4) ? (&bb0.x)[j] : (&bb1.x)[j - 4];
        float h2 = elu1(acc[j] * r + bj);
        float2 w2 = *(const float2*)(W2 + 2 * (fb + j));
        s0 += h2 * w2.x;
        s1 += h2 * w2.y;
    }
    #pragma unroll
    for (int o = 16; o; o >>= 1) {
        s0 += __shfl_xor_sync(0xffffffffu, s0, o);
        s1 += __shfl_xor_sync(0xffffffffu, s1, o);
    }
    if (lane == 0) {
        float as2v = s0 * aS2[0] + s1 * aS2[1];
        float ad2v = s0 * aD2[0] + s1 * aD2[1];
        g_pk[n] = make_float4(as2v, s0, s1, ad2v);
    }
}

// ---------------- layer-2 fused softmax+aggregate (warp per dst, ONE pass) --
__global__ __launch_bounds__(256) void k_agg2f(float* __restrict__ out,
                                               const float* __restrict__ b2) {
    int n = (blockIdx.x * blockDim.x + threadIdx.x) >> 5;
    int lane = threadIdx.x & 31;
    if (n >= NN) return;
    int beg = g_rowptr[n], end = g_rowptr[n + 1];
    float adv = g_pk[n].w;

    float s = 0, p0 = 0, p1 = 0;
    for (int e = beg + lane; e < end; e += 32) {
        int sn = g_csr[e];
        float4 pk = g_pk[sn];
        float ex = __expf(lrelu(pk.x + adv));
        s += ex;
        p0 += ex * pk.y;
        p1 += ex * pk.z;
    }
    #pragma unroll
    for (int o = 16; o; o >>= 1) {
        s  += __shfl_xor_sync(0xffffffffu, s, o);
        p0 += __shfl_xor_sync(0xffffffffu, p0, o);
        p1 += __shfl_xor_sync(0xffffffffu, p1, o);
    }
    if (lane == 0) {
        float inv = 1.f / s;
        out[2 * n]     = p0 * inv + b2[0];
        out[2 * n + 1] = p1 * inv + b2[1];
    }
}

// ---------------- launch ----------------------------------------------------
extern "C" void kernel_launch(void* const* d_in, const int* in_sizes, int n_in,
                              void* d_out, int out_size) {
    const float* x   = (const float*)d_in[0];
    const int*   ei  = (const int*)  d_in[1];
    const float* W1  = (const float*)d_in[2];
    const float* aS1 = (const float*)d_in[3];
    const float* aD1 = (const float*)d_in[4];
    const float* b1  = (const float*)d_in[5];
    const float* W2  = (const float*)d_in[6];
    const float* aS2 = (const float*)d_in[7];
    const float* aD2 = (const float*)d_in[8];
    const float* b2  = (const float*)d_in[9];
    float* out = (float*)d_out;

    // Fork a side stream so GEMM1 (depends only on x, W1) overlaps the CSR
    // build inside the captured graph.
    cudaStream_t s2;
    cudaStreamCreateWithFlags(&s2, cudaStreamNonBlocking);
    cudaEvent_t evFork, evJoin;
    cudaEventCreateWithFlags(&evFork, cudaEventDisableTiming);
    cudaEventCreateWithFlags(&evJoin, cudaEventDisableTiming);

    cudaEventRecord(evFork, 0);
    cudaStreamWaitEvent(s2, evFork, 0);

    // branch A (s2): layer-1 GEMM + fused alphas
    k_gemm1_tc<<<dim3((NN + GBM - 1) / GBM, F2 / GBN), 256, 0, s2>>>(x, W1, aS1, aD1);
    cudaEventRecord(evJoin, s2);

    // branch B (default): CSR build
    void* cntPtr = nullptr;
    cudaGetSymbolAddress(&cntPtr, g_cnt);
    cudaMemsetAsync(cntPtr, 0, NN * sizeof(int), 0);
    k_degree<<<(EE + 255) / 256, 256>>>(ei);
    k_blocksum<<<NBLKS, SCAN_BLK>>>();
    k_scanbsum<<<1, 128>>>();
    k_writeptr<<<NBLKS, SCAN_BLK>>>();
    k_scatter<<<(EE + 255) / 256, 256>>>(ei);

    // join
    cudaStreamWaitEvent(0, evJoin, 0);

    // layer-1 aggregate fused with layer-2 linear
    int warpGrid = (NN * 32 + 255) / 256;
    k_agg1f<<<warpGrid, 256>>>(b1, W2, aS2, aD2);

    // layer-2 aggregate
    k_agg2f<<<warpGrid, 256>>>(out, b2);
}

// round 15
// speedup vs baseline: 1.3333x; 1.1181x over previous
#include <cuda_runtime.h>
#include <cuda_fp16.h>
#include <math.h>
#include <stdint.h>

// Problem constants (fixed by the dataset)
#define NN   100000
#define EE   1600000
#define ETOT (EE + NN)          // edges + self loops
#define F1   128                // input features
#define F2   256                // HEADS*HID
#define NEG_SLOPE 0.2f

#define SCAN_BLK 1024
#define NBLKS ((NN + SCAN_BLK - 1) / SCAN_BLK)   // 98

// ---------------- scratch (device globals; no allocations allowed) ----------
__device__ __half g_h1h[(size_t)NN * F2]; // layer1 linear output, fp16 [N,256]
__device__ float g_as1[NN * 4];
__device__ float g_ad1[NN * 4];
__device__ float4 g_pk[NN];               // {as2, h3.x, h3.y, ad2} per node
__device__ int   g_cnt[NN];
__device__ int   g_rowptr[NN + 1];
__device__ int   g_cursor[NN];
__device__ int   g_bsum[NBLKS];
__device__ int   g_boff[NBLKS];
__device__ int   g_csr[ETOT];             // src node per incoming edge, grouped by dst

__device__ __forceinline__ float lrelu(float x) { return x > 0.f ? x : NEG_SLOPE * x; }
__device__ __forceinline__ float elu1(float x)  { return x > 0.f ? x : expm1f(x); }

// ---------------- CSR construction ------------------------------------------
__global__ void k_degree(const int* __restrict__ ei) {
    int i = blockIdx.x * blockDim.x + threadIdx.x;
    if (i < EE) atomicAdd(&g_cnt[ei[EE + i]], 1);
}

__global__ __launch_bounds__(SCAN_BLK) void k_blocksum() {
    __shared__ int ws[32];
    int i = blockIdx.x * SCAN_BLK + threadIdx.x;
    int v = (i < NN) ? (g_cnt[i] + 1) : 0;
    int s = v;
    #pragma unroll
    for (int o = 16; o; o >>= 1) s += __shfl_xor_sync(0xffffffffu, s, o);
    if ((threadIdx.x & 31) == 0) ws[threadIdx.x >> 5] = s;
    __syncthreads();
    if (threadIdx.x < 32) {
        int t = ws[threadIdx.x];
        #pragma unroll
        for (int o = 16; o; o >>= 1) t += __shfl_xor_sync(0xffffffffu, t, o);
        if (threadIdx.x == 0) g_bsum[blockIdx.x] = t;
    }
}

__global__ void k_scanbsum() {
    __shared__ int sh[NBLKS];
    int t = threadIdx.x;
    if (t < NBLKS) sh[t] = g_bsum[t];
    __syncthreads();
    if (t == 0) {
        int run = 0;
        #pragma unroll 4
        for (int i = 0; i < NBLKS; i++) { int c = sh[i]; sh[i] = run; run += c; }
        g_rowptr[NN] = run;
    }
    __syncthreads();
    if (t < NBLKS) g_boff[t] = sh[t];
}

__global__ __launch_bounds__(SCAN_BLK) void k_writeptr() {
    __shared__ int ws[32];
    const int lane = threadIdx.x & 31;
    const int w    = threadIdx.x >> 5;
    int i = blockIdx.x * SCAN_BLK + threadIdx.x;
    int v = (i < NN) ? (g_cnt[i] + 1) : 0;
    int x = v;
    #pragma unroll
    for (int o = 1; o < 32; o <<= 1) {
        int y = __shfl_up_sync(0xffffffffu, x, o);
        if (lane >= o) x += y;
    }
    if (lane == 31) ws[w] = x;
    __syncthreads();
    if (threadIdx.x < 32) {
        int y = ws[threadIdx.x];
        #pragma unroll
        for (int o = 1; o < 32; o <<= 1) {
            int z = __shfl_up_sync(0xffffffffu, y, o);
            if (lane >= o) y += z;
        }
        ws[threadIdx.x] = y;
    }
    __syncthreads();
    int excl = x - v + ((w > 0) ? ws[w - 1] : 0) + g_boff[blockIdx.x];
    if (i < NN) {
        g_rowptr[i] = excl;
        g_csr[excl] = i;          // self loop in slot 0
        g_cursor[i] = excl + 1;
    }
}

__global__ void k_scatter(const int* __restrict__ ei) {
    int i = blockIdx.x * blockDim.x + threadIdx.x;
    if (i < EE) {
        int s = ei[i];
        int d = ei[EE + i];
        int p = atomicAdd(&g_cursor[d], 1);
        g_csr[p] = s;
    }
}

// ---------------- GEMM1 (fp16 mma.m16n8k16 + ldmatrix) + fused alphas -------
// fp16 has the same 10-bit mantissa as tf32 -> same accuracy class.
#define GBM 128
#define GBN 64
#define GBK 32
#define APAD 40   // halfs per A row (32 + 8): LDSM rows hit distinct banks
#define BPAD 72   // halfs per B row (64 + 8)

__device__ __forceinline__ void ldsm_x4(uint32_t& r0, uint32_t& r1,
                                        uint32_t& r2, uint32_t& r3, uint32_t addr) {
    asm volatile("ldmatrix.sync.aligned.m8n8.x4.shared.b16 {%0,%1,%2,%3}, [%4];"
                 : "=r"(r0), "=r"(r1), "=r"(r2), "=r"(r3) : "r"(addr));
}
__device__ __forceinline__ void ldsm_x2t(uint32_t& r0, uint32_t& r1, uint32_t addr) {
    asm volatile("ldmatrix.sync.aligned.m8n8.x2.trans.shared.b16 {%0,%1}, [%2];"
                 : "=r"(r0), "=r"(r1) : "r"(addr));
}
__device__ __forceinline__ void mma_f16(float* c, uint32_t a0, uint32_t a1,
                                        uint32_t a2, uint32_t a3,
                                        uint32_t b0, uint32_t b1) {
    asm volatile(
        "mma.sync.aligned.m16n8k16.row.col.f32.f16.f16.f32 "
        "{%0,%1,%2,%3}, {%4,%5,%6,%7}, {%8,%9}, {%0,%1,%2,%3};"
        : "+f"(c[0]), "+f"(c[1]), "+f"(c[2]), "+f"(c[3])
        : "r"(a0), "r"(a1), "r"(a2), "r"(a3), "r"(b0), "r"(b1));
}

__global__ __launch_bounds__(256) void k_gemm1_tc(const float* __restrict__ A,
                                                  const float* __restrict__ B,
                                                  const float* __restrict__ aS1,
                                                  const float* __restrict__ aD1) {
    __shared__ __half As[GBM * APAD];     // [row 0..127][k 0..31]
    __shared__ __half Bs[GBK * BPAD];     // [k 0..31][n 0..63]
    __shared__ float sAS[GBM][5];
    __shared__ float sAD[GBM][5];
    const int tid  = threadIdx.x;
    const int wid  = tid >> 5;
    const int lane = tid & 31;
    const int grp  = lane >> 2;
    const int tig  = lane & 3;
    const int wm   = wid & 1;
    const int wn   = wid >> 1;
    const int m0   = blockIdx.x * GBM;
    const int head = blockIdx.y;          // GBN == 64 == one head
    const int n0   = head * GBN;

    const uint32_t asBase = (uint32_t)__cvta_generic_to_shared(As);
    const uint32_t bsBase = (uint32_t)__cvta_generic_to_shared(Bs);
    const int l16 = lane & 15;
    const int khf = (lane >> 4) * 8;      // A col offset for upper half-warp

    float acc[4][2][4];
    #pragma unroll
    for (int i = 0; i < 4; i++)
        #pragma unroll
        for (int j = 0; j < 2; j++)
            #pragma unroll
            for (int k = 0; k < 4; k++) acc[i][j][k] = 0.f;

    float4 pa[4], pb[2];
    auto loadA = [&](int k0, float4* r) {
        #pragma unroll
        for (int i = 0; i < 4; i++) {
            int f = tid + i * 256;
            int row = f >> 3, c4 = f & 7;
            int gr = m0 + row;
            r[i] = (gr < NN) ? *(const float4*)(A + (size_t)gr * F1 + k0 + 4 * c4)
                             : make_float4(0.f, 0.f, 0.f, 0.f);
        }
    };
    auto loadB = [&](int k0, float4* r) {
        #pragma unroll
        for (int i = 0; i < 2; i++) {
            int f = tid + i * 256;
            int row = f >> 4, c4 = f & 15;
            r[i] = *(const float4*)(B + (size_t)(k0 + row) * F2 + n0 + 4 * c4);
        }
    };
    auto cvtStore = [](__half* dst, float4 v) {
        __half2 h01 = __floats2half2_rn(v.x, v.y);
        __half2 h23 = __floats2half2_rn(v.z, v.w);
        uint2 u = make_uint2(*(uint32_t*)&h01, *(uint32_t*)&h23);
        *(uint2*)dst = u;
    };

    loadA(0, pa);
    loadB(0, pb);

    for (int k0 = 0; k0 < F1; k0 += GBK) {
        #pragma unroll
        for (int i = 0; i < 4; i++) {
            int f = tid + i * 256;
            int row = f >> 3, c4 = f & 7;
            cvtStore(As + row * APAD + 4 * c4, pa[i]);
        }
        #pragma unroll
        for (int i = 0; i < 2; i++) {
            int f = tid + i * 256;
            int row = f >> 4, c4 = f & 15;
            cvtStore(Bs + row * BPAD + 4 * c4, pb[i]);
        }
        __syncthreads();

        if (k0 + GBK < F1) {
            loadA(k0 + GBK, pa);
            loadB(k0 + GBK, pb);
        }

        #pragma unroll
        for (int kc = 0; kc < 2; kc++) {
            const int kb = kc * 16;
            uint32_t b[2][2];
            #pragma unroll
            for (int nt = 0; nt < 2; nt++)
                ldsm_x2t(b[nt][0], b[nt][1],
                         bsBase + (uint32_t)(((l16 + kb) * BPAD + wn * 16 + nt * 8) * 2));
            #pragma unroll
            for (int mt = 0; mt < 4; mt++) {
                uint32_t a0, a1, a2, a3;
                ldsm_x4(a0, a1, a2, a3,
                        asBase + (uint32_t)(((wm * 64 + mt * 16 + l16) * APAD + kb + khf) * 2));
                mma_f16(acc[mt][0], a0, a1, a2, a3, b[0][0], b[0][1]);
                mma_f16(acc[mt][1], a0, a1, a2, a3, b[1][0], b[1][1]);
            }
        }
        __syncthreads();
    }

    float asv[2][2], adv[2][2];
    #pragma unroll
    for (int nt = 0; nt < 2; nt++) {
        int c = head * 64 + wn * 16 + nt * 8 + 2 * tig;
        asv[nt][0] = aS1[c];     asv[nt][1] = aS1[c + 1];
        adv[nt][0] = aD1[c];     adv[nt][1] = aD1[c + 1];
    }

    #pragma unroll
    for (int mt = 0; mt < 4; mt++) {
        int r = m0 + wm * 64 + mt * 16 + grp;
        float sS0 = 0.f, sS8 = 0.f, sD0 = 0.f, sD8 = 0.f;
        #pragma unroll
        for (int nt = 0; nt < 2; nt++) {
            int c = n0 + wn * 16 + nt * 8 + 2 * tig;
            if (r < NN)
                *(__half2*)(g_h1h + (size_t)r * F2 + c) =
                    __floats2half2_rn(acc[mt][nt][0], acc[mt][nt][1]);
            if (r + 8 < NN)
                *(__half2*)(g_h1h + (size_t)(r + 8) * F2 + c) =
                    __floats2half2_rn(acc[mt][nt][2], acc[mt][nt][3]);
            sS0 += acc[mt][nt][0] * asv[nt][0] + acc[mt][nt][1] * asv[nt][1];
            sS8 += acc[mt][nt][2] * asv[nt][0] + acc[mt][nt][3] * asv[nt][1];
            sD0 += acc[mt][nt][0] * adv[nt][0] + acc[mt][nt][1] * adv[nt][1];
            sD8 += acc[mt][nt][2] * adv[nt][0] + acc[mt][nt][3] * adv[nt][1];
        }
        #pragma unroll
        for (int o = 1; o <= 2; o <<= 1) {
            sS0 += __shfl_xor_sync(0xffffffffu, sS0, o);
            sS8 += __shfl_xor_sync(0xffffffffu, sS8, o);
            sD0 += __shfl_xor_sync(0xffffffffu, sD0, o);
            sD8 += __shfl_xor_sync(0xffffffffu, sD8, o);
        }
        if (tig == 0) {
            int rl = wm * 64 + mt * 16 + grp;
            sAS[rl][wn] = sS0;  sAS[rl + 8][wn] = sS8;
            sAD[rl][wn] = sD0;  sAD[rl + 8][wn] = sD8;
        }
    }
    __syncthreads();
    if (tid < GBM) {
        int r = m0 + tid;
        if (r < NN) {
            float aS = sAS[tid][0] + sAS[tid][1] + sAS[tid][2] + sAS[tid][3];
            float aD = sAD[tid][0] + sAD[tid][1] + sAD[tid][2] + sAD[tid][3];
            g_as1[4 * r + head] = aS;
            g_ad1[4 * r + head] = aD;
        }
    }
}

// ---------------- layer-1 softmax+aggregate + layer-2 linear (warp per dst) -
__global__ __launch_bounds__(256) void k_agg1f(const float* __restrict__ b1,
                                               const float* __restrict__ W2,
                                               const float* __restrict__ aS2,
                                               const float* __restrict__ aD2) {
    int n = (blockIdx.x * blockDim.x + threadIdx.x) >> 5;
    int lane = threadIdx.x & 31;
    if (n >= NN) return;
    int beg = g_rowptr[n], end = g_rowptr[n + 1];
    const int head = lane >> 3;
    float ad_h = g_ad1[4 * n + head];
    const __half* h1base = g_h1h + 8 * lane;

    float acc[8] = {0, 0, 0, 0, 0, 0, 0, 0};
    float ssum = 0.f;

    int e = beg;
    for (; e + 8 <= end; e += 8) {
        int   si[8];
        float av[8];
        uint4 hv[8];
        #pragma unroll
        for (int k = 0; k < 8; k++) si[k] = g_csr[e + k];
        #pragma unroll
        for (int k = 0; k < 8; k++) av[k] = g_as1[4 * si[k] + head];
        #pragma unroll
        for (int k = 0; k < 8; k++) hv[k] = *(const uint4*)(h1base + (size_t)si[k] * F2);
        #pragma unroll
        for (int k = 0; k < 8; k++) {
            float w = __expf(lrelu(av[k] + ad_h));
            ssum += w;
            const __half2* hp = (const __half2*)&hv[k];
            #pragma unroll
            for (int j = 0; j < 4; j++) {
                float2 f = __half22float2(hp[j]);
                acc[2 * j]     += f.x * w;
                acc[2 * j + 1] += f.y * w;
            }
        }
    }
    for (; e < end; e++) {
        int s = g_csr[e];
        float w = __expf(lrelu(g_as1[4 * s + head] + ad_h));
        uint4 hvv = *(const uint4*)(h1base + (size_t)s * F2);
        const __half2* hp = (const __half2*)&hvv;
        ssum += w;
        #pragma unroll
        for (int j = 0; j < 4; j++) {
            float2 f = __half22float2(hp[j]);
            acc[2 * j]     += f.x * w;
            acc[2 * j + 1] += f.y * w;
        }
    }
    float r = 1.f / ssum;

    const int fb = 8 * lane;
    float4 bb0 = *(const float4*)(b1 + fb);
    float4 bb1 = *(const float4*)(b1 + fb + 4);
    float s0 = 0.f, s1 = 0.f;
    #pragma unroll
    for (int j = 0; j < 8; j++) {
        float bj = (j < 4) ? (&bb0.x)[j] : (&bb1.x)[j - 4];
        float h2 = elu1(acc[j] * r + bj);
        float2 w2 = *(const float2*)(W2 + 2 * (fb + j));
        s0 += h2 * w2.x;
        s1 += h2 * w2.y;
    }
    #pragma unroll
    for (int o = 16; o; o >>= 1) {
        s0 += __shfl_xor_sync(0xffffffffu, s0, o);
        s1 += __shfl_xor_sync(0xffffffffu, s1, o);
    }
    if (lane == 0) {
        float as2v = s0 * aS2[0] + s1 * aS2[1];
        float ad2v = s0 * aD2[0] + s1 * aD2[1];
        g_pk[n] = make_float4(as2v, s0, s1, ad2v);
    }
}

// ---------------- layer-2 fused softmax+aggregate (16 lanes per dst) --------
__global__ __launch_bounds__(256) void k_agg2f(float* __restrict__ out,
                                               const float* __restrict__ b2) {
    int t = blockIdx.x * blockDim.x + threadIdx.x;
    int n = t >> 4;
    int l = t & 15;
    if (n >= NN) return;
    int beg = g_rowptr[n], end = g_rowptr[n + 1];
    float adv = g_pk[n].w;

    float s = 0, p0 = 0, p1 = 0;
    for (int e = beg + l; e < end; e += 16) {
        int sn = g_csr[e];
        float4 pk = g_pk[sn];
        float ex = __expf(lrelu(pk.x + adv));
        s += ex;
        p0 += ex * pk.y;
        p1 += ex * pk.z;
    }
    #pragma unroll
    for (int o = 8; o; o >>= 1) {
        s  += __shfl_xor_sync(0xffffffffu, s, o);
        p0 += __shfl_xor_sync(0xffffffffu, p0, o);
        p1 += __shfl_xor_sync(0xffffffffu, p1, o);
    }
    if (l == 0) {
        float inv = 1.f / s;
        out[2 * n]     = p0 * inv + b2[0];
        out[2 * n + 1] = p1 * inv + b2[1];
    }
}

// ---------------- launch ----------------------------------------------------
extern "C" void kernel_launch(void* const* d_in, const int* in_sizes, int n_in,
                              void* d_out, int out_size) {
    const float* x   = (const float*)d_in[0];
    const int*   ei  = (const int*)  d_in[1];
    const float* W1  = (const float*)d_in[2];
    const float* aS1 = (const float*)d_in[3];
    const float* aD1 = (const float*)d_in[4];
    const float* b1  = (const float*)d_in[5];
    const float* W2  = (const float*)d_in[6];
    const float* aS2 = (const float*)d_in[7];
    const float* aD2 = (const float*)d_in[8];
    const float* b2  = (const float*)d_in[9];
    float* out = (float*)d_out;

    // Fork a side stream so GEMM1 (depends only on x, W1) overlaps the CSR
    // build inside the captured graph.
    cudaStream_t s2;
    cudaStreamCreateWithFlags(&s2, cudaStreamNonBlocking);
    cudaEvent_t evFork, evJoin;
    cudaEventCreateWithFlags(&evFork, cudaEventDisableTiming);
    cudaEventCreateWithFlags(&evJoin, cudaEventDisableTiming);

    cudaEventRecord(evFork, 0);
    cudaStreamWaitEvent(s2, evFork, 0);

    // branch A (s2): layer-1 GEMM + fused alphas
    k_gemm1_tc<<<dim3((NN + GBM - 1) / GBM, F2 / GBN), 256, 0, s2>>>(x, W1, aS1, aD1);
    cudaEventRecord(evJoin, s2);

    // branch B (default): CSR build
    void* cntPtr = nullptr;
    cudaGetSymbolAddress(&cntPtr, g_cnt);
    cudaMemsetAsync(cntPtr, 0, NN * sizeof(int), 0);
    k_degree<<<(EE + 255) / 256, 256>>>(ei);
    k_blocksum<<<NBLKS, SCAN_BLK>>>();
    k_scanbsum<<<1, 128>>>();
    k_writeptr<<<NBLKS, SCAN_BLK>>>();
    k_scatter<<<(EE + 255) / 256, 256>>>(ei);

    // join
    cudaStreamWaitEvent(0, evJoin, 0);

    // layer-1 aggregate fused with layer-2 linear
    int warpGrid = (NN * 32 + 255) / 256;
    k_agg1f<<<warpGrid, 256>>>(b1, W2, aS2, aD2);

    // layer-2 aggregate (16 lanes per node)
    k_agg2f<<<(NN * 16 + 255) / 256, 256>>>(out, b2);
}